// round 4
// baseline (speedup 1.0000x reference)
#include <cuda_runtime.h>
#include <math.h>

#define B_ 64
#define L_ 512
#define D_ 768
#define S_ 8

// ---------------- device scratch (allocation-free) ----------------
__device__ float g_sent[B_ * 4 * D_];    // rows: s5,s6,s7, zero-pad row
__device__ float g_xc1[128 * 2304];      // conv1 im2col: [b*2+p][e*3+k]
__device__ float g_x2[B_ * 2304];        // conv2 im2col: [b][e*3+k] (k=2 tap zero)
__device__ float g_A1[B_ * D_];          // tanh(sent7@gc1_w + b1)
__device__ float g_accA1[B_ * D_];       // split-K accumulators
__device__ float g_accC1[128 * D_];
__device__ float g_accG2[B_ * D_];
__device__ float g_accC2[B_ * D_];

// ---------------- K1: segment means for rows 5,6,7 + zero accumulators ----------------
__global__ void __launch_bounds__(192) k_sent(const float* __restrict__ bert,
                                              const int* __restrict__ seg) {
    int bid = blockIdx.x;
    int t = threadIdx.x;
    if (bid >= 192) {
        // zero the split-K accumulators
        int zt = (bid - 192) * 192 + t;
        const int stride = 240 * 192;
        for (int i = zt; i < B_ * D_;  i += stride) g_accA1[i] = 0.f;
        for (int i = zt; i < 128 * D_; i += stride) g_accC1[i] = 0.f;
        for (int i = zt; i < B_ * D_;  i += stride) g_accG2[i] = 0.f;
        for (int i = zt; i < B_ * D_;  i += stride) g_accC2[i] = 0.f;
        return;
    }
    int b = bid / 3, r = bid % 3, s = 5 + r;
    int start = seg[b * 9 + s];
    int end   = seg[b * 9 + s + 1];
    const float4* base = (const float4*)(bert + (size_t)b * L_ * D_);
    float4 a0 = make_float4(0.f, 0.f, 0.f, 0.f), a1 = a0, a2 = a0, a3 = a0;
    int l = start;
    for (; l + 4 <= end; l += 4) {
        float4 v0 = base[(l + 0) * 192 + t];
        float4 v1 = base[(l + 1) * 192 + t];
        float4 v2 = base[(l + 2) * 192 + t];
        float4 v3 = base[(l + 3) * 192 + t];
        a0.x += v0.x; a0.y += v0.y; a0.z += v0.z; a0.w += v0.w;
        a1.x += v1.x; a1.y += v1.y; a1.z += v1.z; a1.w += v1.w;
        a2.x += v2.x; a2.y += v2.y; a2.z += v2.z; a2.w += v2.w;
        a3.x += v3.x; a3.y += v3.y; a3.z += v3.z; a3.w += v3.w;
    }
    for (; l < end; ++l) {
        float4 v = base[l * 192 + t];
        a0.x += v.x; a0.y += v.y; a0.z += v.z; a0.w += v.w;
    }
    float inv = 1.f / (float)(end - start);
    float4 out;
    out.x = (a0.x + a1.x + a2.x + a3.x) * inv;
    out.y = (a0.y + a1.y + a2.y + a3.y) * inv;
    out.z = (a0.z + a1.z + a2.z + a3.z) * inv;
    out.w = (a0.w + a1.w + a2.w + a3.w) * inv;
    ((float4*)g_sent)[b * 768 + r * 192 + t] = out;   // 768 float4 per batch
    if (r == 2)
        ((float4*)g_sent)[b * 768 + 3 * 192 + t] = make_float4(0.f, 0.f, 0.f, 0.f);
}

// ---------------- K2: build conv1 im2col (kk = e*3+k, matches conv weight layout) ----------------
__global__ void __launch_bounds__(256) k_xc1() {
    int r = blockIdx.x;           // 0..127
    int b = r >> 1, p = r & 1;    // p = position - 6
    const float* sb = g_sent + b * 3072 + p * 768;  // tap k reads row p+k (row 3 = zeros)
    float* xrow = g_xc1 + r * 2304;
    for (int e = threadIdx.x; e < 768; e += 256) {
        xrow[e * 3 + 0] = sb[e];
        xrow[e * 3 + 1] = sb[768 + e];
        xrow[e * 3 + 2] = sb[1536 + e];
    }
}

// ---------------- tiled split-K GEMM body: C[M,768] += A[M,K] @ W ----------------
// BT=0: W is [K,768] (n contiguous, gc weights). BT=1: W is [768,K] (k contiguous, conv weights).
template <int BT>
__device__ __forceinline__ void gemm_body(
    const float* __restrict__ A, int lda,
    const float* __restrict__ W, float* __restrict__ C,
    int K, int nNt, int nMt, int kslice, int bid,
    float (*As)[33], float (*Bs)[68])
{
    int nt = bid % nNt;
    int mt = (bid / nNt) % nMt;
    int ks = bid / (nNt * nMt);
    int k0 = ks * kslice;
    int k1 = k0 + kslice;

    int tid = threadIdx.x;
    int tx = tid & 15, ty = tid >> 4;
    int n0 = nt * 64;
    const float* Ab = A + (size_t)(mt * 64) * lda;

    float acc[4][4];
#pragma unroll
    for (int i = 0; i < 4; i++)
#pragma unroll
        for (int j = 0; j < 4; j++) acc[i][j] = 0.f;

    for (int kb = k0; kb < k1; kb += 32) {
        {   // A tile 64x32, coalesced along k, store [m][k]
            int k = tid & 31, m = tid >> 5;
#pragma unroll
            for (int j = 0; j < 8; j++)
                As[m + j * 8][k] = Ab[(size_t)(m + j * 8) * lda + kb + k];
        }
        if (BT == 0) {  // W[K,768], coalesced float4 along n
            int n4 = tid & 15, k = tid >> 4;
#pragma unroll
            for (int j = 0; j < 2; j++) {
                float4 v = *(const float4*)&W[(size_t)(kb + k + j * 16) * 768 + n0 + n4 * 4];
                *(float4*)&Bs[k + j * 16][n4 * 4] = v;
            }
        } else {        // W[768,K], coalesced along k, transpose into smem
            int k = tid & 31, n = tid >> 5;
#pragma unroll
            for (int j = 0; j < 8; j++)
                Bs[k][n + j * 8] = W[(size_t)(n0 + n + j * 8) * K + kb + k];
        }
        __syncthreads();
#pragma unroll
        for (int kk = 0; kk < 32; kk++) {
            float a0 = As[ty * 4 + 0][kk];
            float a1 = As[ty * 4 + 1][kk];
            float a2 = As[ty * 4 + 2][kk];
            float a3 = As[ty * 4 + 3][kk];
            float4 bv = *(const float4*)&Bs[kk][tx * 4];
            acc[0][0] += a0 * bv.x; acc[0][1] += a0 * bv.y; acc[0][2] += a0 * bv.z; acc[0][3] += a0 * bv.w;
            acc[1][0] += a1 * bv.x; acc[1][1] += a1 * bv.y; acc[1][2] += a1 * bv.z; acc[1][3] += a1 * bv.w;
            acc[2][0] += a2 * bv.x; acc[2][1] += a2 * bv.y; acc[2][2] += a2 * bv.z; acc[2][3] += a2 * bv.w;
            acc[3][0] += a3 * bv.x; acc[3][1] += a3 * bv.y; acc[3][2] += a3 * bv.z; acc[3][3] += a3 * bv.w;
        }
        __syncthreads();
    }
    float* Cb = C + (size_t)(mt * 64) * 768 + n0;
#pragma unroll
    for (int i = 0; i < 4; i++)
#pragma unroll
        for (int j = 0; j < 4; j++)
            atomicAdd(&Cb[(ty * 4 + i) * 768 + tx * 4 + j], acc[i][j]);
}

// stage 1: gemm1 (sent7 @ gc1_w) + conv1 (Xc1 @ conv1_w^T). blocks: 48 + 288 = 336
__global__ void __launch_bounds__(256) k_stage1(const float* __restrict__ gc1_w,
                                                const float* __restrict__ conv1_w) {
    __shared__ float As[64][33];
    __shared__ float Bs[32][68];
    if ((int)blockIdx.x < 48) {
        // A = sentence row 7 of each batch: base g_sent+1536, lda=3072, M=64, K=768, 4 k-splits
        gemm_body<0>(g_sent + 1536, 3072, gc1_w, g_accA1, 768, 12, 1, 192, blockIdx.x, As, Bs);
    } else {
        // conv1: M=128, K=2304, 12 k-splits
        gemm_body<1>(g_xc1, 2304, conv1_w, g_accC1, 2304, 12, 2, 192, blockIdx.x - 48, As, Bs);
    }
}

// stage 2: gemm2 (A1 @ gc2_w) + conv2 (X2 @ conv2_w^T). blocks: 48 + 144 = 192
__global__ void __launch_bounds__(256) k_stage2(const float* __restrict__ gc2_w,
                                                const float* __restrict__ conv2_w) {
    __shared__ float As[64][33];
    __shared__ float Bs[32][68];
    if ((int)blockIdx.x < 48) {
        gemm_body<0>(g_A1, 768, gc2_w, g_accG2, 768, 12, 1, 192, blockIdx.x, As, Bs);
    } else {
        gemm_body<1>(g_x2, 2304, conv2_w, g_accC2, 2304, 12, 1, 192, blockIdx.x - 48, As, Bs);
    }
}

// ---------------- K4: epilogue of stage1 + build conv2 im2col ----------------
__global__ void __launch_bounds__(256) k_mid(const float* __restrict__ gc1_b,
                                             const float* __restrict__ conv1_b) {
    int b = blockIdx.x;
    for (int d = threadIdx.x; d < 768; d += 256) {
        g_A1[b * 768 + d] = tanhf(g_accA1[b * 768 + d] + gc1_b[d]);
        float c0 = tanhf(g_accC1[(b * 2 + 0) * 768 + d] + conv1_b[d]);  // conv1 @ pos 6
        float c1 = tanhf(g_accC1[(b * 2 + 1) * 768 + d] + conv1_b[d]);  // conv1 @ pos 7
        float* x = g_x2 + b * 2304 + d * 3;
        x[0] = c0; x[1] = c1; x[2] = 0.f;   // tap k=2 of conv2@pos7 is padding
    }
}

// ---------------- block reduction (broadcast to all threads) ----------------
__device__ __forceinline__ float warpSum(float v) {
#pragma unroll
    for (int o = 16; o; o >>= 1) v += __shfl_down_sync(0xffffffffu, v, o);
    return v;
}
__device__ __forceinline__ float blockSum(float v) {
    __shared__ float red[8];
    int lane = threadIdx.x & 31, w = threadIdx.x >> 5;
    v = warpSum(v);
    __syncthreads();            // protect red from previous call / order prior smem reads
    if (lane == 0) red[w] = v;
    __syncthreads();
    float s = 0.f;
#pragma unroll
    for (int i = 0; i < 8; i++) s += red[i];
    return s;
}

// ---------------- K6: hops + softmax + fc2, one block per batch ----------------
__global__ void __launch_bounds__(256) k_final(
    const float* __restrict__ target, const float* __restrict__ gc2_b,
    const float* __restrict__ conv2_b, const float* __restrict__ ln_g,
    const float* __restrict__ ln_b, const float* __restrict__ fc2_w,
    const float* __restrict__ fc2_b, float* __restrict__ out)
{
    int b = blockIdx.x;
    int tid = threadIdx.x;
    __shared__ float s7[768];
    __shared__ float vbuf[768];
    __shared__ float ak[3][768];

    for (int d = tid; d < 768; d += 256) s7[d] = g_sent[b * 3072 + 2 * 768 + d];
    __syncthreads();

    // ||s7||^2 for the tmask branch
    float p = 0.f;
    for (int d = tid; d < 768; d += 256) p += s7[d] * s7[d];
    float ss = blockSum(p);

    for (int kbr = 0; kbr < 3; kbr++) {
        for (int d = tid; d < 768; d += 256) {
            float v;
            if (kbr == 0)      v = tanhf(g_accG2[b * 768 + d] + gc2_b[d]);    // g2 last row
            else if (kbr == 1) v = tanhf(g_accC2[b * 768 + d] + conv2_b[d]);  // conv_out last row
            else               v = 1.f / (1.f + expf(-ss * s7[d]));           // tmask last row
            vbuf[d] = v;
        }
        __syncthreads();
        for (int it = 0; it < 2; it++) {   // HOP-1 iterations, last-row only
            float pc = 0.f;
            for (int d = tid; d < 768; d += 256) pc += vbuf[d] * s7[d];
            float c = blockSum(pc);
            float u[3], su = 0.f, sq = 0.f;
#pragma unroll
            for (int i = 0; i < 3; i++) {
                int d = tid + i * 256;
                float x = 1.f / (1.f + expf(-c * s7[d]));
                u[i] = x; su += x; sq += x * x;
            }
            float mean = blockSum(su) * (1.f / 768.f);
            float m2   = blockSum(sq) * (1.f / 768.f);
            float rstd = rsqrtf(m2 - mean * mean + 1e-5f);
#pragma unroll
            for (int i = 0; i < 3; i++) {
                int d = tid + i * 256;
                vbuf[d] = 0.5f * ((u[i] - mean) * rstd * ln_g[d] + ln_b[d]) + s7[d];
            }
            __syncthreads();
        }
        for (int d = tid; d < 768; d += 256) ak[kbr][d] = vbuf[d];
        __syncthreads();
    }

    // softmax weights vs target[0]
    float tk[3];
    for (int k = 0; k < 3; k++) {
        float p2 = 0.f;
        for (int d = tid; d < 768; d += 256) p2 += ak[k][d] * target[d];
        tk[k] = blockSum(p2);
    }
    float mx = fmaxf(tk[0], fmaxf(tk[1], tk[2]));
    float e0 = expf(tk[0] - mx), e1 = expf(tk[1] - mx), e2 = expf(tk[2] - mx);
    float inv = 1.f / (e0 + e1 + e2);
    float w0 = e0 * inv, w1 = e1 * inv, w2 = e2 * inv;

    float pj[3] = {0.f, 0.f, 0.f};
    for (int d = tid; d < 768; d += 256) {
        float f0 = w0 * ak[0][d], f1 = w1 * ak[1][d], f2 = w2 * ak[2][d];
#pragma unroll
        for (int j = 0; j < 3; j++)
            pj[j] += f0 * fc2_w[d * 3 + j]
                   + f1 * fc2_w[(768 + d) * 3 + j]
                   + f2 * fc2_w[(1536 + d) * 3 + j];
    }
    for (int j = 0; j < 3; j++) {
        float s = blockSum(pj[j]);
        if (tid == 0) out[b * 3 + j] = s + fc2_b[j];
    }
}

// ---------------- launch ----------------
extern "C" void kernel_launch(void* const* d_in, const int* in_sizes, int n_in,
                              void* d_out, int out_size) {
    (void)in_sizes; (void)n_in; (void)out_size;
    const float* bert    = (const float*)d_in[0];
    const float* target  = (const float*)d_in[1];
    const float* gc1_w   = (const float*)d_in[2];
    const float* gc1_b   = (const float*)d_in[3];
    const float* gc2_w   = (const float*)d_in[4];
    const float* gc2_b   = (const float*)d_in[5];
    const float* conv1_w = (const float*)d_in[6];
    const float* conv1_b = (const float*)d_in[7];
    const float* conv2_w = (const float*)d_in[8];
    const float* conv2_b = (const float*)d_in[9];
    const float* ln_g    = (const float*)d_in[10];
    const float* ln_b    = (const float*)d_in[11];
    const float* fc2_w   = (const float*)d_in[12];
    const float* fc2_b   = (const float*)d_in[13];
    const int*   seg     = (const int*)d_in[14];
    float* out = (float*)d_out;

    k_sent<<<432, 192>>>(bert, seg);          // segment means + zero accumulators
    k_xc1<<<128, 256>>>();                    // conv1 im2col
    k_stage1<<<336, 256>>>(gc1_w, conv1_w);   // gemm1 + conv1 (split-K, atomics)
    k_mid<<<64, 256>>>(gc1_b, conv1_b);       // tanh epilogue + conv2 im2col
    k_stage2<<<192, 256>>>(gc2_w, conv2_w);   // gemm2 + conv2
    k_final<<<64, 256>>>(target, gc2_b, conv2_b, ln_g, ln_b, fc2_w, fc2_b, out);
}

// round 5
// speedup vs baseline: 1.0093x; 1.0093x over previous
#include <cuda_runtime.h>
#include <math.h>

#define B_ 64
#define L_ 512
#define D_ 768
#define S_ 8

// ---------------- device scratch (allocation-free) ----------------
__device__ float g_sent[B_ * 4 * D_];    // rows per batch: s5,s6,s7, zero-pad
__device__ float g_accA1[B_ * D_];       // split-K accumulators (atomicAdd targets)
__device__ float g_accC1[128 * D_];      // conv1 out @ pos {6,7} per batch
__device__ float g_accG2[B_ * D_];
__device__ float g_accC2[B_ * D_];

// packed f32x2 FMA (sm_103a: only reachable via PTX)
#define FMA2(acc, a, b) \
    asm("fma.rn.f32x2 %0, %1, %2, %0;" : "+l"(acc) : "l"(a), "l"(b))

// ---------------- K1: segment means for rows 5,6,7 + zero accumulators ----------------
__global__ void __launch_bounds__(192) k_sent(const float* __restrict__ bert,
                                              const int* __restrict__ seg) {
    int bid = blockIdx.x;
    int t = threadIdx.x;
    if (bid >= 192) {
        int zt = (bid - 192) * 192 + t;
        const int stride = 240 * 192;
        for (int i = zt; i < B_ * D_;  i += stride) g_accA1[i] = 0.f;
        for (int i = zt; i < 128 * D_; i += stride) g_accC1[i] = 0.f;
        for (int i = zt; i < B_ * D_;  i += stride) g_accG2[i] = 0.f;
        for (int i = zt; i < B_ * D_;  i += stride) g_accC2[i] = 0.f;
        return;
    }
    int b = bid / 3, r = bid % 3, s = 5 + r;
    int start = seg[b * 9 + s];
    int end   = seg[b * 9 + s + 1];
    const float4* base = (const float4*)(bert + (size_t)b * L_ * D_);
    float4 a[8];
#pragma unroll
    for (int i = 0; i < 8; i++) a[i] = make_float4(0.f, 0.f, 0.f, 0.f);
    int l = start;
    for (; l + 8 <= end; l += 8) {
#pragma unroll
        for (int i = 0; i < 8; i++) {
            float4 v = base[(l + i) * 192 + t];
            a[i].x += v.x; a[i].y += v.y; a[i].z += v.z; a[i].w += v.w;
        }
    }
    for (; l < end; ++l) {
        float4 v = base[l * 192 + t];
        a[0].x += v.x; a[0].y += v.y; a[0].z += v.z; a[0].w += v.w;
    }
#pragma unroll
    for (int i = 1; i < 8; i++) {
        a[0].x += a[i].x; a[0].y += a[i].y; a[0].z += a[i].z; a[0].w += a[i].w;
    }
    float inv = 1.f / (float)(end - start);
    float4 out = make_float4(a[0].x * inv, a[0].y * inv, a[0].z * inv, a[0].w * inv);
    ((float4*)g_sent)[b * 768 + r * 192 + t] = out;
    if (r == 2)
        ((float4*)g_sent)[b * 768 + 3 * 192 + t] = make_float4(0.f, 0.f, 0.f, 0.f);
}

// ---------------- tiled split-K GEMM with on-the-fly A and packed f32x2 FMA ----------------
// C[M,768] += A[M,K] @ W.  64x64 block tile, 4x4 per thread, split-K via atomicAdd.
// MODE 0 (G1): A(m,k) = g_sent row7 of batch m                     W = gc1_w  [K,768]
// MODE 1 (C1): A(r,kk) = conv1 im2col from g_sent                  W = conv1_w [768,K]
// MODE 2 (G2): A(m,k) = tanh(g_accA1 + gc1_b)                      W = gc2_w  [K,768]
// MODE 3 (C2): A(b,kk) = conv2 im2col = tanh(g_accC1 + conv1_b)    W = conv2_w [768,K]
template <int MODE>
__device__ __forceinline__ void gemm_body2(
    const float* __restrict__ W, float* __restrict__ C,
    const float* __restrict__ bias,
    int K, int nNt, int nMt, int kslice, int bid,
    float2 (*As2)[33], float (*Bs)[68])
{
    constexpr bool BT = (MODE == 1 || MODE == 3);   // conv weights: [768, K] k-contiguous
    int nt = bid % nNt;
    int mt = (bid / nNt) % nMt;
    int ks = bid / (nNt * nMt);
    int k0 = ks * kslice;
    int k1 = k0 + kslice;

    int tid = threadIdx.x;
    int tx = tid & 15, ty = tid >> 4;
    int n0 = nt * 64;
    int mbase = mt * 64;

    unsigned long long acc[4][2] = {};

    for (int kb = k0; kb < k1; kb += 32) {
        {   // ---- A tile 64x32, value duplicated into float2 ----
            int ka = tid & 31, m0 = tid >> 5;
            int kg = kb + ka;
            int e = 0, tap = 0;
            float bk = 0.f;
            if (MODE == 1 || MODE == 3) { e = kg / 3; tap = kg - e * 3; }
            if (MODE == 2) bk = bias[kg];
            if (MODE == 3) bk = bias[e];
#pragma unroll
            for (int j = 0; j < 8; j++) {
                int m = mbase + m0 + j * 8;
                float v;
                if (MODE == 0) {
                    v = g_sent[m * 3072 + 1536 + kg];
                } else if (MODE == 1) {
                    v = g_sent[(m >> 1) * 3072 + ((m & 1) + tap) * 768 + e];
                } else if (MODE == 2) {
                    v = tanhf(g_accA1[m * 768 + kg] + bk);
                } else {
                    v = (tap == 2) ? 0.f
                        : tanhf(g_accC1[(m * 2 + tap) * 768 + e] + bk);
                }
                As2[m0 + j * 8][ka] = make_float2(v, v);
            }
        }
        if (!BT) {  // W[K,768], coalesced float4 along n
            int n4 = tid & 15, k = tid >> 4;
#pragma unroll
            for (int j = 0; j < 2; j++) {
                float4 v = *(const float4*)&W[(size_t)(kb + k + j * 16) * 768 + n0 + n4 * 4];
                *(float4*)&Bs[k + j * 16][n4 * 4] = v;
            }
        } else {    // W[768,K], coalesced along k, transpose into smem
            int k = tid & 31, n = tid >> 5;
#pragma unroll
            for (int j = 0; j < 8; j++)
                Bs[k][n + j * 8] = W[(size_t)(n0 + n + j * 8) * K + kb + k];
        }
        __syncthreads();
#pragma unroll
        for (int kk = 0; kk < 32; kk++) {
            unsigned long long a0 = *(const unsigned long long*)&As2[ty * 4 + 0][kk];
            unsigned long long a1 = *(const unsigned long long*)&As2[ty * 4 + 1][kk];
            unsigned long long a2 = *(const unsigned long long*)&As2[ty * 4 + 2][kk];
            unsigned long long a3 = *(const unsigned long long*)&As2[ty * 4 + 3][kk];
            ulonglong2 bb = *(const ulonglong2*)&Bs[kk][tx * 4];
            FMA2(acc[0][0], a0, bb.x); FMA2(acc[0][1], a0, bb.y);
            FMA2(acc[1][0], a1, bb.x); FMA2(acc[1][1], a1, bb.y);
            FMA2(acc[2][0], a2, bb.x); FMA2(acc[2][1], a2, bb.y);
            FMA2(acc[3][0], a3, bb.x); FMA2(acc[3][1], a3, bb.y);
        }
        __syncthreads();
    }
    float* Cb = C + (size_t)mbase * 768 + n0;
#pragma unroll
    for (int i = 0; i < 4; i++) {
        float2 p0 = *(float2*)&acc[i][0];
        float2 p1 = *(float2*)&acc[i][1];
        float* row = &Cb[(ty * 4 + i) * 768 + tx * 4];
        atomicAdd(&row[0], p0.x);
        atomicAdd(&row[1], p0.y);
        atomicAdd(&row[2], p1.x);
        atomicAdd(&row[3], p1.y);
    }
}

// stage 1: gemm1 (48 blocks) + conv1 im2col-on-the-fly (288 blocks)
__global__ void __launch_bounds__(256) k_stage1(const float* __restrict__ gc1_w,
                                                const float* __restrict__ conv1_w) {
    __shared__ __align__(16) float2 As2[64][33];
    __shared__ __align__(16) float  Bs[32][68];
    if ((int)blockIdx.x < 48)
        gemm_body2<0>(gc1_w, g_accA1, nullptr, 768, 12, 1, 192, blockIdx.x, As2, Bs);
    else
        gemm_body2<1>(conv1_w, g_accC1, nullptr, 2304, 12, 2, 192, blockIdx.x - 48, As2, Bs);
}

// stage 2: gemm2 with fused tanh-epilogue A (48) + conv2 with fused epilogue+im2col A (144)
__global__ void __launch_bounds__(256) k_stage2(const float* __restrict__ gc2_w,
                                                const float* __restrict__ conv2_w,
                                                const float* __restrict__ gc1_b,
                                                const float* __restrict__ conv1_b) {
    __shared__ __align__(16) float2 As2[64][33];
    __shared__ __align__(16) float  Bs[32][68];
    if ((int)blockIdx.x < 48)
        gemm_body2<2>(gc2_w, g_accG2, gc1_b, 768, 12, 1, 192, blockIdx.x, As2, Bs);
    else
        gemm_body2<3>(conv2_w, g_accC2, conv1_b, 2304, 12, 1, 192, blockIdx.x - 48, As2, Bs);
}

// ---------------- block reduction (broadcast to all threads) ----------------
__device__ __forceinline__ float warpSum(float v) {
#pragma unroll
    for (int o = 16; o; o >>= 1) v += __shfl_down_sync(0xffffffffu, v, o);
    return v;
}
__device__ __forceinline__ float blockSum(float v) {
    __shared__ float red[8];
    int lane = threadIdx.x & 31, w = threadIdx.x >> 5;
    v = warpSum(v);
    __syncthreads();
    if (lane == 0) red[w] = v;
    __syncthreads();
    float s = 0.f;
#pragma unroll
    for (int i = 0; i < 8; i++) s += red[i];
    return s;
}

// ---------------- K4: hops + softmax + fc2, one block per batch ----------------
__global__ void __launch_bounds__(256) k_final(
    const float* __restrict__ target, const float* __restrict__ gc2_b,
    const float* __restrict__ conv2_b, const float* __restrict__ ln_g,
    const float* __restrict__ ln_b, const float* __restrict__ fc2_w,
    const float* __restrict__ fc2_b, float* __restrict__ out)
{
    int b = blockIdx.x;
    int tid = threadIdx.x;
    __shared__ float s7[768];
    __shared__ float vbuf[768];
    __shared__ float ak[3][768];

    for (int d = tid; d < 768; d += 256) s7[d] = g_sent[b * 3072 + 2 * 768 + d];
    __syncthreads();

    float p = 0.f;
    for (int d = tid; d < 768; d += 256) p += s7[d] * s7[d];
    float ss = blockSum(p);

    for (int kbr = 0; kbr < 3; kbr++) {
        for (int d = tid; d < 768; d += 256) {
            float v;
            if (kbr == 0)      v = tanhf(g_accG2[b * 768 + d] + gc2_b[d]);
            else if (kbr == 1) v = tanhf(g_accC2[b * 768 + d] + conv2_b[d]);
            else               v = 1.f / (1.f + expf(-ss * s7[d]));
            vbuf[d] = v;
        }
        __syncthreads();
        for (int it = 0; it < 2; it++) {
            float pc = 0.f;
            for (int d = tid; d < 768; d += 256) pc += vbuf[d] * s7[d];
            float c = blockSum(pc);
            float u[3], su = 0.f, sq = 0.f;
#pragma unroll
            for (int i = 0; i < 3; i++) {
                int d = tid + i * 256;
                float x = 1.f / (1.f + expf(-c * s7[d]));
                u[i] = x; su += x; sq += x * x;
            }
            float mean = blockSum(su) * (1.f / 768.f);
            float m2   = blockSum(sq) * (1.f / 768.f);
            float rstd = rsqrtf(m2 - mean * mean + 1e-5f);
#pragma unroll
            for (int i = 0; i < 3; i++) {
                int d = tid + i * 256;
                vbuf[d] = 0.5f * ((u[i] - mean) * rstd * ln_g[d] + ln_b[d]) + s7[d];
            }
            __syncthreads();
        }
        for (int d = tid; d < 768; d += 256) ak[kbr][d] = vbuf[d];
        __syncthreads();
    }

    float tk[3];
    for (int k = 0; k < 3; k++) {
        float p2 = 0.f;
        for (int d = tid; d < 768; d += 256) p2 += ak[k][d] * target[d];
        tk[k] = blockSum(p2);
    }
    float mx = fmaxf(tk[0], fmaxf(tk[1], tk[2]));
    float e0 = expf(tk[0] - mx), e1 = expf(tk[1] - mx), e2 = expf(tk[2] - mx);
    float inv = 1.f / (e0 + e1 + e2);
    float w0 = e0 * inv, w1 = e1 * inv, w2 = e2 * inv;

    float pj[3] = {0.f, 0.f, 0.f};
    for (int d = tid; d < 768; d += 256) {
        float f0 = w0 * ak[0][d], f1 = w1 * ak[1][d], f2 = w2 * ak[2][d];
#pragma unroll
        for (int j = 0; j < 3; j++)
            pj[j] += f0 * fc2_w[d * 3 + j]
                   + f1 * fc2_w[(768 + d) * 3 + j]
                   + f2 * fc2_w[(1536 + d) * 3 + j];
    }
    for (int j = 0; j < 3; j++) {
        float s = blockSum(pj[j]);
        if (tid == 0) out[b * 3 + j] = s + fc2_b[j];
    }
}

// ---------------- launch ----------------
extern "C" void kernel_launch(void* const* d_in, const int* in_sizes, int n_in,
                              void* d_out, int out_size) {
    (void)in_sizes; (void)n_in; (void)out_size;
    const float* bert    = (const float*)d_in[0];
    const float* target  = (const float*)d_in[1];
    const float* gc1_w   = (const float*)d_in[2];
    const float* gc1_b   = (const float*)d_in[3];
    const float* gc2_w   = (const float*)d_in[4];
    const float* gc2_b   = (const float*)d_in[5];
    const float* conv1_w = (const float*)d_in[6];
    const float* conv1_b = (const float*)d_in[7];
    const float* conv2_w = (const float*)d_in[8];
    const float* conv2_b = (const float*)d_in[9];
    const float* ln_g    = (const float*)d_in[10];
    const float* ln_b    = (const float*)d_in[11];
    const float* fc2_w   = (const float*)d_in[12];
    const float* fc2_b   = (const float*)d_in[13];
    const int*   seg     = (const int*)d_in[14];
    float* out = (float*)d_out;

    k_sent<<<432, 192>>>(bert, seg);                          // means + zero accumulators
    k_stage1<<<336, 256>>>(gc1_w, conv1_w);                   // gemm1 + conv1 (fused im2col)
    k_stage2<<<192, 256>>>(gc2_w, conv2_w, gc1_b, conv1_b);   // gemm2 + conv2 (fused epilogue)
    k_final<<<64, 256>>>(target, gc2_b, conv2_b, ln_g, ln_b, fc2_w, fc2_b, out);
}

// round 6
// speedup vs baseline: 1.1162x; 1.1060x over previous
#include <cuda_runtime.h>
#include <math.h>

#define B_ 64
#define L_ 512
#define D_ 768
#define S_ 8

// ---------------- device scratch (allocation-free) ----------------
__device__ float g_sent[B_ * 4 * D_];    // rows per batch: s5,s6,s7, zero-pad
__device__ float g_accA1[B_ * D_];       // split-K accumulators (atomicAdd targets)
__device__ float g_accC1[128 * D_];      // conv1 out @ pos {6,7} per batch
__device__ float g_accG2[B_ * D_];
__device__ float g_accC2[B_ * D_];

// packed f32x2 FMA (sm_103a: only reachable via PTX)
#define FMA2(acc, a, b) \
    asm("fma.rn.f32x2 %0, %1, %2, %0;" : "+l"(acc) : "l"(a), "l"(b))

// ---------------- K1: segment means (rows 5,6,7), 2 D-halves per row + zeroing ----------------
// compute blocks: 384 = b(64) x r(3) x half(2); zero blocks: 160. blockDim = 96.
__global__ void __launch_bounds__(96) k_sent(const float* __restrict__ bert,
                                             const int* __restrict__ seg) {
    int bid = blockIdx.x;
    int t = threadIdx.x;
    if (bid >= 384) {
        int zt = (bid - 384) * 96 + t;
        const int stride = 160 * 96;
        for (int i = zt; i < B_ * D_;  i += stride) g_accA1[i] = 0.f;
        for (int i = zt; i < 128 * D_; i += stride) g_accC1[i] = 0.f;
        for (int i = zt; i < B_ * D_;  i += stride) g_accG2[i] = 0.f;
        for (int i = zt; i < B_ * D_;  i += stride) g_accC2[i] = 0.f;
        return;
    }
    int half = bid & 1;
    int r = (bid >> 1) % 3;
    int b = bid / 6;
    int s = 5 + r;
    int start = seg[b * 9 + s];
    int end   = seg[b * 9 + s + 1];
    int col = half * 96 + t;               // float4 column 0..191
    const float4* base = (const float4*)(bert + (size_t)b * L_ * D_);
    float4 a[8];
#pragma unroll
    for (int i = 0; i < 8; i++) a[i] = make_float4(0.f, 0.f, 0.f, 0.f);
    int l = start;
    for (; l + 8 <= end; l += 8) {
#pragma unroll
        for (int i = 0; i < 8; i++) {
            float4 v = base[(l + i) * 192 + col];
            a[i].x += v.x; a[i].y += v.y; a[i].z += v.z; a[i].w += v.w;
        }
    }
    for (; l < end; ++l) {
        float4 v = base[l * 192 + col];
        a[0].x += v.x; a[0].y += v.y; a[0].z += v.z; a[0].w += v.w;
    }
#pragma unroll
    for (int i = 1; i < 8; i++) {
        a[0].x += a[i].x; a[0].y += a[i].y; a[0].z += a[i].z; a[0].w += a[i].w;
    }
    float inv = 1.f / (float)(end - start);
    float4 outv = make_float4(a[0].x * inv, a[0].y * inv, a[0].z * inv, a[0].w * inv);
    ((float4*)g_sent)[b * 768 + r * 192 + col] = outv;
    if (r == 2)
        ((float4*)g_sent)[b * 768 + 3 * 192 + col] = make_float4(0.f, 0.f, 0.f, 0.f);
}

// ---------------- tiled split-K GEMM with on-the-fly A and packed f32x2 FMA ----------------
template <int MODE>
__device__ __forceinline__ void gemm_body2(
    const float* __restrict__ W, float* __restrict__ C,
    const float* __restrict__ bias,
    int K, int nNt, int nMt, int kslice, int bid,
    float2 (*As2)[33], float (*Bs)[68])
{
    constexpr bool BT = (MODE == 1 || MODE == 3);   // conv weights: [768, K] k-contiguous
    int nt = bid % nNt;
    int mt = (bid / nNt) % nMt;
    int ks = bid / (nNt * nMt);
    int k0 = ks * kslice;
    int k1 = k0 + kslice;

    int tid = threadIdx.x;
    int tx = tid & 15, ty = tid >> 4;
    int n0 = nt * 64;
    int mbase = mt * 64;

    unsigned long long acc[4][2] = {};

    for (int kb = k0; kb < k1; kb += 32) {
        {   // ---- A tile 64x32, value duplicated into float2 ----
            int ka = tid & 31, m0 = tid >> 5;
            int kg = kb + ka;
            int e = 0, tap = 0;
            float bk = 0.f;
            if (MODE == 1 || MODE == 3) { e = kg / 3; tap = kg - e * 3; }
            if (MODE == 2) bk = bias[kg];
            if (MODE == 3) bk = bias[e];
#pragma unroll
            for (int j = 0; j < 8; j++) {
                int m = mbase + m0 + j * 8;
                float v;
                if (MODE == 0) {
                    v = g_sent[m * 3072 + 1536 + kg];
                } else if (MODE == 1) {
                    v = g_sent[(m >> 1) * 3072 + ((m & 1) + tap) * 768 + e];
                } else if (MODE == 2) {
                    v = tanhf(g_accA1[m * 768 + kg] + bk);
                } else {
                    v = (tap == 2) ? 0.f
                        : tanhf(g_accC1[(m * 2 + tap) * 768 + e] + bk);
                }
                As2[m0 + j * 8][ka] = make_float2(v, v);
            }
        }
        if (!BT) {  // W[K,768], coalesced float4 along n
            int n4 = tid & 15, k = tid >> 4;
#pragma unroll
            for (int j = 0; j < 2; j++) {
                float4 v = *(const float4*)&W[(size_t)(kb + k + j * 16) * 768 + n0 + n4 * 4];
                *(float4*)&Bs[k + j * 16][n4 * 4] = v;
            }
        } else {    // W[768,K], coalesced along k, transpose into smem
            int k = tid & 31, n = tid >> 5;
#pragma unroll
            for (int j = 0; j < 8; j++)
                Bs[k][n + j * 8] = W[(size_t)(n0 + n + j * 8) * K + kb + k];
        }
        __syncthreads();
#pragma unroll
        for (int kk = 0; kk < 32; kk++) {
            unsigned long long a0 = *(const unsigned long long*)&As2[ty * 4 + 0][kk];
            unsigned long long a1 = *(const unsigned long long*)&As2[ty * 4 + 1][kk];
            unsigned long long a2 = *(const unsigned long long*)&As2[ty * 4 + 2][kk];
            unsigned long long a3 = *(const unsigned long long*)&As2[ty * 4 + 3][kk];
            ulonglong2 bb = *(const ulonglong2*)&Bs[kk][tx * 4];
            FMA2(acc[0][0], a0, bb.x); FMA2(acc[0][1], a0, bb.y);
            FMA2(acc[1][0], a1, bb.x); FMA2(acc[1][1], a1, bb.y);
            FMA2(acc[2][0], a2, bb.x); FMA2(acc[2][1], a2, bb.y);
            FMA2(acc[3][0], a3, bb.x); FMA2(acc[3][1], a3, bb.y);
        }
        __syncthreads();
    }
    float* Cb = C + (size_t)mbase * 768 + n0;
#pragma unroll
    for (int i = 0; i < 4; i++) {
        float2 p0 = *(float2*)&acc[i][0];
        float2 p1 = *(float2*)&acc[i][1];
        float* row = &Cb[(ty * 4 + i) * 768 + tx * 4];
        atomicAdd(&row[0], p0.x);
        atomicAdd(&row[1], p0.y);
        atomicAdd(&row[2], p1.x);
        atomicAdd(&row[3], p1.y);
    }
}

// stage 1: gemm1 (48 blocks) + conv1 im2col-on-the-fly (288 blocks)
__global__ void __launch_bounds__(256) k_stage1(const float* __restrict__ gc1_w,
                                                const float* __restrict__ conv1_w) {
    __shared__ __align__(16) float2 As2[64][33];
    __shared__ __align__(16) float  Bs[32][68];
    if ((int)blockIdx.x < 48)
        gemm_body2<0>(gc1_w, g_accA1, nullptr, 768, 12, 1, 192, blockIdx.x, As2, Bs);
    else
        gemm_body2<1>(conv1_w, g_accC1, nullptr, 2304, 12, 2, 192, blockIdx.x - 48, As2, Bs);
}

// stage 2: gemm2 with fused tanh-epilogue A (48) + conv2 with fused epilogue+im2col A (144)
__global__ void __launch_bounds__(256) k_stage2(const float* __restrict__ gc2_w,
                                                const float* __restrict__ conv2_w,
                                                const float* __restrict__ gc1_b,
                                                const float* __restrict__ conv1_b) {
    __shared__ __align__(16) float2 As2[64][33];
    __shared__ __align__(16) float  Bs[32][68];
    if ((int)blockIdx.x < 48)
        gemm_body2<2>(gc2_w, g_accG2, gc1_b, 768, 12, 1, 192, blockIdx.x, As2, Bs);
    else
        gemm_body2<3>(conv2_w, g_accC2, conv1_b, 2304, 12, 1, 192, blockIdx.x - 48, As2, Bs);
}

// ---------------- warp all-reduce helpers ----------------
__device__ __forceinline__ float warpAllSum(float v) {
#pragma unroll
    for (int o = 16; o; o >>= 1) v += __shfl_xor_sync(0xffffffffu, v, o);
    return v;
}
__device__ __forceinline__ void warpAllSum2(float& a, float& b) {
#pragma unroll
    for (int o = 16; o; o >>= 1) {
        a += __shfl_xor_sync(0xffffffffu, a, o);
        b += __shfl_xor_sync(0xffffffffu, b, o);
    }
}
__device__ __forceinline__ void warpAllSum3(float& a, float& b, float& c) {
#pragma unroll
    for (int o = 16; o; o >>= 1) {
        a += __shfl_xor_sync(0xffffffffu, a, o);
        b += __shfl_xor_sync(0xffffffffu, b, o);
        c += __shfl_xor_sync(0xffffffffu, c, o);
    }
}

// ---------------- K4: hops + softmax + fc2. grid=64, block=96 (warp per branch) ----------------
__global__ void __launch_bounds__(96) k_final(
    const float* __restrict__ target, const float* __restrict__ gc2_b,
    const float* __restrict__ conv2_b, const float* __restrict__ ln_g,
    const float* __restrict__ ln_b, const float* __restrict__ fc2_w,
    const float* __restrict__ fc2_b, float* __restrict__ out)
{
    int b = blockIdx.x;
    int w = threadIdx.x >> 5;        // branch id: 0=g2, 1=conv, 2=tmask
    int lane = threadIdx.x & 31;

    __shared__ float ak[3][768];
    __shared__ float tks[3];

    float s7[24], v[24];
#pragma unroll
    for (int i = 0; i < 24; i++)
        s7[i] = g_sent[b * 3072 + 1536 + lane + i * 32];

    // branch init
    if (w == 2) {
        float ss = 0.f;
#pragma unroll
        for (int i = 0; i < 24; i++) ss += s7[i] * s7[i];
        ss = warpAllSum(ss);
#pragma unroll
        for (int i = 0; i < 24; i++)
            v[i] = __fdividef(1.f, 1.f + __expf(-ss * s7[i]));
    } else {
        const float* acc  = (w == 0) ? g_accG2 : g_accC2;
        const float* bias = (w == 0) ? gc2_b : conv2_b;
#pragma unroll
        for (int i = 0; i < 24; i++) {
            int d = lane + i * 32;
            v[i] = tanhf(acc[b * 768 + d] + bias[d]);
        }
    }

    // 2 hop-refine iterations (warp-local, no barriers)
#pragma unroll
    for (int it = 0; it < 2; it++) {
        float pc = 0.f;
#pragma unroll
        for (int i = 0; i < 24; i++) pc += v[i] * s7[i];
        float c = warpAllSum(pc);
        float x[24], su = 0.f, sq = 0.f;
#pragma unroll
        for (int i = 0; i < 24; i++) {
            float xv = __fdividef(1.f, 1.f + __expf(-c * s7[i]));
            x[i] = xv; su += xv; sq += xv * xv;
        }
        warpAllSum2(su, sq);
        float mean = su * (1.f / 768.f);
        float m2   = sq * (1.f / 768.f);
        float rstd = rsqrtf(m2 - mean * mean + 1e-5f);
#pragma unroll
        for (int i = 0; i < 24; i++) {
            int d = lane + i * 32;
            v[i] = 0.5f * ((x[i] - mean) * rstd * ln_g[d] + ln_b[d]) + s7[i];
        }
    }

    // publish branch result + its target-dot
    float pt = 0.f;
#pragma unroll
    for (int i = 0; i < 24; i++) {
        int d = lane + i * 32;
        ak[w][d] = v[i];
        pt += v[i] * target[d];
    }
    pt = warpAllSum(pt);
    if (lane == 0) tks[w] = pt;
    __syncthreads();

    // warp 0: softmax weights + fc2
    if (w == 0) {
        float t0 = tks[0], t1 = tks[1], t2 = tks[2];
        float mx = fmaxf(t0, fmaxf(t1, t2));
        float e0 = __expf(t0 - mx), e1 = __expf(t1 - mx), e2 = __expf(t2 - mx);
        float inv = __fdividef(1.f, e0 + e1 + e2);
        float w0 = e0 * inv, w1 = e1 * inv, w2 = e2 * inv;

        float pj0 = 0.f, pj1 = 0.f, pj2 = 0.f;
#pragma unroll
        for (int i = 0; i < 24; i++) {
            int d = lane + i * 32;
            float f0 = w0 * ak[0][d];
            float f1 = w1 * ak[1][d];
            float f2 = w2 * ak[2][d];
            const float* w_0 = &fc2_w[d * 3];
            const float* w_1 = &fc2_w[(768 + d) * 3];
            const float* w_2 = &fc2_w[(1536 + d) * 3];
            pj0 += f0 * w_0[0] + f1 * w_1[0] + f2 * w_2[0];
            pj1 += f0 * w_0[1] + f1 * w_1[1] + f2 * w_2[1];
            pj2 += f0 * w_0[2] + f1 * w_1[2] + f2 * w_2[2];
        }
        warpAllSum3(pj0, pj1, pj2);
        if (lane == 0) {
            out[b * 3 + 0] = pj0 + fc2_b[0];
            out[b * 3 + 1] = pj1 + fc2_b[1];
            out[b * 3 + 2] = pj2 + fc2_b[2];
        }
    }
}

// ---------------- launch ----------------
extern "C" void kernel_launch(void* const* d_in, const int* in_sizes, int n_in,
                              void* d_out, int out_size) {
    (void)in_sizes; (void)n_in; (void)out_size;
    const float* bert    = (const float*)d_in[0];
    const float* target  = (const float*)d_in[1];
    const float* gc1_w   = (const float*)d_in[2];
    const float* gc1_b   = (const float*)d_in[3];
    const float* gc2_w   = (const float*)d_in[4];
    const float* gc2_b   = (const float*)d_in[5];
    const float* conv1_w = (const float*)d_in[6];
    const float* conv1_b = (const float*)d_in[7];
    const float* conv2_w = (const float*)d_in[8];
    const float* conv2_b = (const float*)d_in[9];
    const float* ln_g    = (const float*)d_in[10];
    const float* ln_b    = (const float*)d_in[11];
    const float* fc2_w   = (const float*)d_in[12];
    const float* fc2_b   = (const float*)d_in[13];
    const int*   seg     = (const int*)d_in[14];
    float* out = (float*)d_out;

    k_sent<<<544, 96>>>(bert, seg);                           // means (384) + zeroing (160)
    k_stage1<<<336, 256>>>(gc1_w, conv1_w);                   // gemm1 + conv1 (fused im2col)
    k_stage2<<<192, 256>>>(gc2_w, conv2_w, gc1_b, conv1_b);   // gemm2 + conv2 (fused epilogue)
    k_final<<<64, 96>>>(target, gc2_b, conv2_b, ln_g, ln_b, fc2_w, fc2_b, out);
}